// round 2
// baseline (speedup 1.0000x reference)
#include <cuda_runtime.h>
#include <cuda_bf16.h>
#include <mma.h>
#include <math.h>

using namespace nvcuda;

// Problem constants
#define TOK   4096          // B*S tokens
#define DM    1024          // d_model
#define NE    8             // experts
#define KSEL  2             // top-k
#define HD    4096          // expert dim
#define PD    256           // proj dim
#define TK    (TOK*KSEL)    // 8192 token-expert rows
#define CLAMP_MAX 4.6051701859880914f

// ---------------- device scratch (static; no allocation) ----------------
__device__ float g_proj[TOK*PD];                 // 4 MB
__device__ int   g_topk_e[TK];
__device__ float g_topk_w[TK];
__device__ float g_sumw[TOK];
__device__ int   g_count[NE];
__device__ int   g_offset[NE+1];
__device__ int   g_tileoff[NE+1];
__device__ int   g_cursor[NE];
__device__ int   g_token_of_row[TK];
__device__ float g_w_of_row[TK];
__device__ float g_H[(size_t)TK*HD];             // 134 MB
__device__ float g_frac_acc[NE];
__device__ float g_inv_simnorm[NE];
__device__ float g_scale;

// ---------------- small utility kernels ----------------
__global__ void reset_kernel() {
    int i = threadIdx.x;
    if (i < NE) { g_count[i] = 0; g_frac_acc[i] = 0.f; }
}

__global__ void prep_kernel(const float* __restrict__ sim, const float* __restrict__ temp) {
    // 8 warps: warp w computes column norm of sim[:, w] (P=256 rows)
    int w = threadIdx.x >> 5, lane = threadIdx.x & 31;
    float ss = 0.f;
    for (int i = 0; i < PD/32; i++) {
        float v = sim[(lane + 32*i)*NE + w];
        ss += v*v;
    }
    #pragma unroll
    for (int off = 16; off; off >>= 1) ss += __shfl_xor_sync(0xffffffff, ss, off);
    if (lane == 0) g_inv_simnorm[w] = 1.f / fmaxf(sqrtf(ss), 1e-12f);
    if (threadIdx.x == 0) g_scale = expf(fminf(temp[0], CLAMP_MAX));
}

// ---------------- projection: proj = x @ Wp^T + bp (fp32 SIMT, exact) ----------------
__global__ void proj_kernel(const float* __restrict__ x, const float* __restrict__ Wp,
                            const float* __restrict__ bp) {
    const int BM = 64, BN = 64, BK = 16;
    __shared__ float Xs[BK][BM+2];
    __shared__ float Ws[BK][BN+2];
    int m0 = blockIdx.x * BM, n0 = blockIdx.y * BN;
    int tid = threadIdx.x;
    int ty = tid >> 4, tx = tid & 15;
    float acc[4][4];
    #pragma unroll
    for (int i = 0; i < 4; i++)
        #pragma unroll
        for (int j = 0; j < 4; j++) acc[i][j] = 0.f;

    for (int k0 = 0; k0 < DM; k0 += BK) {
        for (int idx = tid; idx < BM*BK; idx += 256) {
            int m = idx >> 4, k = idx & 15;
            Xs[k][m] = x[(size_t)(m0+m)*DM + k0 + k];
            Ws[k][m] = Wp[(size_t)(n0+m)*DM + k0 + k];
        }
        __syncthreads();
        #pragma unroll
        for (int k = 0; k < BK; k++) {
            float a[4], b[4];
            #pragma unroll
            for (int i = 0; i < 4; i++) a[i] = Xs[k][ty*4+i];
            #pragma unroll
            for (int j = 0; j < 4; j++) b[j] = Ws[k][tx*4+j];
            #pragma unroll
            for (int i = 0; i < 4; i++)
                #pragma unroll
                for (int j = 0; j < 4; j++) acc[i][j] += a[i]*b[j];
        }
        __syncthreads();
    }
    #pragma unroll
    for (int i = 0; i < 4; i++)
        #pragma unroll
        for (int j = 0; j < 4; j++) {
            int n = n0 + tx*4 + j;
            g_proj[(size_t)(m0+ty*4+i)*PD + n] = acc[i][j] + bp[n];
        }
}

// ---------------- gating: softmax over cosine sims, top-2, routing stats ----------------
__global__ void gate_kernel(const float* __restrict__ sim) {
    int t = blockIdx.x * 8 + (threadIdx.x >> 5);
    int lane = threadIdx.x & 31;
    float pv[PD/32];
    float ss = 0.f;
    #pragma unroll
    for (int i = 0; i < PD/32; i++) {
        pv[i] = g_proj[(size_t)t*PD + lane + 32*i];
        ss += pv[i]*pv[i];
    }
    #pragma unroll
    for (int off = 16; off; off >>= 1) ss += __shfl_xor_sync(0xffffffff, ss, off);
    float inv_pn = 1.f / fmaxf(sqrtf(ss), 1e-12f);
    float scale = g_scale;
    float logit[NE];
    #pragma unroll
    for (int e = 0; e < NE; e++) {
        float d = 0.f;
        #pragma unroll
        for (int i = 0; i < PD/32; i++)
            d += pv[i] * sim[(lane + 32*i)*NE + e];
        #pragma unroll
        for (int off = 16; off; off >>= 1) d += __shfl_xor_sync(0xffffffff, d, off);
        logit[e] = d * inv_pn * g_inv_simnorm[e] * scale;
    }
    // softmax
    float mx = logit[0];
    #pragma unroll
    for (int e = 1; e < NE; e++) mx = fmaxf(mx, logit[e]);
    float pr[NE], se = 0.f;
    #pragma unroll
    for (int e = 0; e < NE; e++) { pr[e] = expf(logit[e]-mx); se += pr[e]; }
    float inv_se = 1.f / se;
    #pragma unroll
    for (int e = 0; e < NE; e++) pr[e] *= inv_se;
    // top-2 (lowest index wins ties, matching lax.top_k)
    int i0 = 0;
    #pragma unroll
    for (int e = 1; e < NE; e++) if (pr[e] > pr[i0]) i0 = e;
    int i1 = (i0 == 0) ? 1 : 0;
    #pragma unroll
    for (int e = 0; e < NE; e++) if (e != i0 && pr[e] > pr[i1]) i1 = e;
    float s = pr[i0] + pr[i1] + 1e-8f;
    float w0 = pr[i0]/s, w1 = pr[i1]/s;
    if (lane == 0) {
        g_topk_e[t*2]   = i0; g_topk_e[t*2+1] = i1;
        g_topk_w[t*2]   = w0; g_topk_w[t*2+1] = w1;
        g_sumw[t] = w0 + w1;
        atomicAdd(&g_count[i0], 1);
        atomicAdd(&g_count[i1], 1);
    }
    if (lane < NE) atomicAdd(&g_frac_acc[lane], pr[lane]);
}

__global__ void scan_kernel() {
    int off = 0, toff = 0;
    for (int e = 0; e < NE; e++) {
        g_offset[e]  = off;
        g_tileoff[e] = toff;
        g_cursor[e]  = off;
        off  += g_count[e];
        toff += (g_count[e] + 63) >> 6;
    }
    g_offset[NE]  = off;
    g_tileoff[NE] = toff;
}

__global__ void build_kernel() {
    int i = blockIdx.x * blockDim.x + threadIdx.x;
    if (i >= TK) return;
    int e = g_topk_e[i];
    int row = atomicAdd(&g_cursor[e], 1);
    g_token_of_row[row] = i >> 1;
    g_w_of_row[row]     = g_topk_w[i];
}

__global__ void init_out_kernel(const float* __restrict__ x, float* __restrict__ out) {
    size_t i = (size_t)blockIdx.x * blockDim.x + threadIdx.x;
    out[i] = g_sumw[i >> 10] * x[i];
}

// ---------------- TF32 WMMA grouped GEMMs ----------------
// GEMM tile: BM=64, BN=64, BK=32; 8 warps (2x4 of 32x16 warp tiles)
#define GLD 40   // smem leading dim (multiple of 8)
#define CLD 68

__global__ void gemm1_kernel(const float* __restrict__ x, const float* __restrict__ A,
                             const float* __restrict__ a_bias) {
    __shared__ float sh[2*64*GLD];           // Xs | Bs, reused as Cs
    __shared__ int   s_tok[64];
    float* Xs = sh;
    float* Bs = sh + 64*GLD;

    int bt = blockIdx.x;
    if (bt >= g_tileoff[NE]) return;
    int e = 0;
    while (bt >= g_tileoff[e+1]) e++;
    int mloc = bt - g_tileoff[e];
    int rowbase = g_offset[e] + mloc*64;
    int nrows = g_count[e] - mloc*64; if (nrows > 64) nrows = 64;
    int n0 = blockIdx.y * 64;
    int tid = threadIdx.x;
    int wid = tid >> 5;
    int wm = wid & 1, wn = wid >> 1;

    if (tid < 64) s_tok[tid] = (tid < nrows) ? g_token_of_row[rowbase + tid] : -1;
    __syncthreads();

    const float* Aex = A + (size_t)e*HD*DM;
    wmma::fragment<wmma::accumulator,16,16,8,float> c0, c1;
    wmma::fill_fragment(c0, 0.f);
    wmma::fill_fragment(c1, 0.f);

    for (int k0 = 0; k0 < DM; k0 += 32) {
        for (int idx = tid; idx < 64*32; idx += 256) {
            int m = idx >> 5, k = idx & 31;
            int tkn = s_tok[m];
            Xs[m*GLD + k] = (tkn >= 0) ? x[(size_t)tkn*DM + k0 + k] : 0.f;
            Bs[m*GLD + k] = Aex[(size_t)(n0 + m)*DM + k0 + k];
        }
        __syncthreads();
        #pragma unroll
        for (int kk = 0; kk < 32; kk += 8) {
            wmma::fragment<wmma::matrix_a,16,16,8,wmma::precision::tf32,wmma::row_major> a0, a1;
            wmma::fragment<wmma::matrix_b,16,16,8,wmma::precision::tf32,wmma::col_major> b;
            wmma::load_matrix_sync(a0, &Xs[(wm*32)*GLD + kk], GLD);
            wmma::load_matrix_sync(a1, &Xs[(wm*32+16)*GLD + kk], GLD);
            wmma::load_matrix_sync(b,  &Bs[(wn*16)*GLD + kk], GLD);
            #pragma unroll
            for (int i = 0; i < a0.num_elements; i++) {
                a0.x[i] = wmma::__float_to_tf32(a0.x[i]);
                a1.x[i] = wmma::__float_to_tf32(a1.x[i]);
            }
            #pragma unroll
            for (int i = 0; i < b.num_elements; i++) b.x[i] = wmma::__float_to_tf32(b.x[i]);
            wmma::mma_sync(c0, a0, b, c0);
            wmma::mma_sync(c1, a1, b, c1);
        }
        __syncthreads();
    }
    float* Cs = sh;
    wmma::store_matrix_sync(&Cs[(wm*32)*CLD + wn*16], c0, CLD, wmma::mem_row_major);
    wmma::store_matrix_sync(&Cs[(wm*32+16)*CLD + wn*16], c1, CLD, wmma::mem_row_major);
    __syncthreads();
    for (int idx = tid; idx < 64*64; idx += 256) {
        int r = idx >> 6, n = idx & 63;
        if (r < nrows)
            g_H[(size_t)(rowbase+r)*HD + n0 + n] = Cs[r*CLD + n] + a_bias[(size_t)e*HD + n0 + n];
    }
}

__global__ void gemm2_kernel(const float* __restrict__ Bw, const float* __restrict__ b_bias,
                             float* __restrict__ out) {
    __shared__ float sh[2*64*GLD];
    __shared__ int   s_tok[64];
    __shared__ float s_w[64];
    float* Xs = sh;
    float* Bs = sh + 64*GLD;

    int bt = blockIdx.x;
    if (bt >= g_tileoff[NE]) return;
    int e = 0;
    while (bt >= g_tileoff[e+1]) e++;
    int mloc = bt - g_tileoff[e];
    int rowbase = g_offset[e] + mloc*64;
    int nrows = g_count[e] - mloc*64; if (nrows > 64) nrows = 64;
    int n0 = blockIdx.y * 64;
    int tid = threadIdx.x;
    int wid = tid >> 5;
    int wm = wid & 1, wn = wid >> 1;

    if (tid < 64) {
        s_tok[tid] = (tid < nrows) ? g_token_of_row[rowbase + tid] : -1;
        s_w[tid]   = (tid < nrows) ? g_w_of_row[rowbase + tid] : 0.f;
    }
    __syncthreads();

    const float* Bex = Bw + (size_t)e*DM*HD;
    wmma::fragment<wmma::accumulator,16,16,8,float> c0, c1;
    wmma::fill_fragment(c0, 0.f);
    wmma::fill_fragment(c1, 0.f);

    for (int k0 = 0; k0 < HD; k0 += 32) {
        for (int idx = tid; idx < 64*32; idx += 256) {
            int m = idx >> 5, k = idx & 31;
            Xs[m*GLD + k] = (s_tok[m] >= 0) ? g_H[(size_t)(rowbase+m)*HD + k0 + k] : 0.f;
            Bs[m*GLD + k] = Bex[(size_t)(n0 + m)*HD + k0 + k];
        }
        __syncthreads();
        #pragma unroll
        for (int kk = 0; kk < 32; kk += 8) {
            wmma::fragment<wmma::matrix_a,16,16,8,wmma::precision::tf32,wmma::row_major> a0, a1;
            wmma::fragment<wmma::matrix_b,16,16,8,wmma::precision::tf32,wmma::col_major> b;
            wmma::load_matrix_sync(a0, &Xs[(wm*32)*GLD + kk], GLD);
            wmma::load_matrix_sync(a1, &Xs[(wm*32+16)*GLD + kk], GLD);
            wmma::load_matrix_sync(b,  &Bs[(wn*16)*GLD + kk], GLD);
            #pragma unroll
            for (int i = 0; i < a0.num_elements; i++) {
                a0.x[i] = wmma::__float_to_tf32(a0.x[i]);
                a1.x[i] = wmma::__float_to_tf32(a1.x[i]);
            }
            #pragma unroll
            for (int i = 0; i < b.num_elements; i++) b.x[i] = wmma::__float_to_tf32(b.x[i]);
            wmma::mma_sync(c0, a0, b, c0);
            wmma::mma_sync(c1, a1, b, c1);
        }
        __syncthreads();
    }
    float* Cs = sh;
    wmma::store_matrix_sync(&Cs[(wm*32)*CLD + wn*16], c0, CLD, wmma::mem_row_major);
    wmma::store_matrix_sync(&Cs[(wm*32+16)*CLD + wn*16], c1, CLD, wmma::mem_row_major);
    __syncthreads();
    for (int idx = tid; idx < 64*64; idx += 256) {
        int r = idx >> 6, n = idx & 63;
        if (r < nrows) {
            float v = Cs[r*CLD + n] + b_bias[(size_t)e*DM + n0 + n];
            atomicAdd(&out[(size_t)s_tok[r]*DM + n0 + n], s_w[r] * v);
        }
    }
}

__global__ void finalize_kernel(float* __restrict__ out) {
    if (threadIdx.x != 0) return;
    const size_t base = (size_t)TOK * DM;
    float aux = 0.f;
    for (int e = 0; e < NE; e++) {
        float fr = g_frac_acc[e] / (float)TOK;
        float d = fr - 1.f/(float)NE;
        aux += d*d;
        out[base + 1 + e]  = fr;
        out[base + 9 + e]  = (float)g_count[e];
    }
    out[base] = aux;
}

// ---------------- launch ----------------
extern "C" void kernel_launch(void* const* d_in, const int* in_sizes, int n_in,
                              void* d_out, int out_size) {
    const float* x      = (const float*)d_in[0];
    const float* Wp     = (const float*)d_in[1];
    const float* bp     = (const float*)d_in[2];
    const float* sim    = (const float*)d_in[3];
    const float* temp   = (const float*)d_in[4];
    const float* A      = (const float*)d_in[5];
    const float* a_bias = (const float*)d_in[6];
    const float* Bw     = (const float*)d_in[7];
    const float* b_bias = (const float*)d_in[8];
    float* out = (float*)d_out;

    reset_kernel<<<1, 32>>>();
    prep_kernel<<<1, 256>>>(sim, temp);
    proj_kernel<<<dim3(TOK/64, PD/64), 256>>>(x, Wp, bp);
    gate_kernel<<<TOK/8, 256>>>(sim);
    scan_kernel<<<1, 1>>>();
    build_kernel<<<TK/256, 256>>>();
    init_out_kernel<<<(TOK*DM)/256, 256>>>(x, out);
    // max m-tiles = TK/64 + (NE-... ) <= 128 + 8 = 136
    gemm1_kernel<<<dim3(136, HD/64), 256>>>(x, A, a_bias);
    gemm2_kernel<<<dim3(136, DM/64), 256>>>(Bw, b_bias, out);
    finalize_kernel<<<1, 32>>>(out);
}

// round 6
// speedup vs baseline: 2.9366x; 2.9366x over previous
#include <cuda_runtime.h>
#include <cuda_bf16.h>
#include <mma.h>
#include <math.h>
#include <cstdint>
#include <cstddef>

using namespace nvcuda;

// Problem constants
#define TOK   4096          // B*S tokens
#define DM    1024          // d_model
#define NE    8             // experts
#define KSEL  2             // top-k
#define HD    4096          // expert dim
#define PD    256           // proj dim
#define TK    (TOK*KSEL)    // 8192 token-expert rows
#define CLAMP_MAX 4.6051701859880914f

// GEMM tiling
#define BMM 128
#define BNN 128
#define BKK 32
#define XLD 36              // smem leading dim (36 floats = 144B, 16B-aligned rows, conflict-spread)
#define CLD 132             // epilogue staging leading dim
#define NTILES 72           // max m-tiles: TK/128 + NE
#define GEMM_SMEM (4*128*XLD*4)   // 73728 B (2 X bufs + 2 B bufs); staging 128*132*4=67584 reuses it

// ---------------- device scratch (static; no allocation) ----------------
__device__ float g_proj[TOK*PD];
__device__ int   g_topk_e[TK];
__device__ float g_topk_w[TK];
__device__ float g_sumw[TOK];
__device__ int   g_count[NE];
__device__ int   g_offset[NE+1];
__device__ int   g_tileoff[NE+1];
__device__ int   g_cursor[NE];
__device__ int   g_token_of_row[TK];
__device__ float g_w_of_row[TK];
__device__ float g_H[(size_t)TK*HD];             // 134 MB
__device__ float g_frac_acc[NE];
__device__ float g_inv_simnorm[NE];
__device__ float g_scale;

// ---------------- cp.async helpers ----------------
__device__ __forceinline__ void cp_async16(float* smem_dst, const float* gsrc, int src_bytes) {
    unsigned int s = (unsigned int)__cvta_generic_to_shared(smem_dst);
    asm volatile("cp.async.cg.shared.global [%0], [%1], 16, %2;\n"
                 :: "r"(s), "l"(gsrc), "r"(src_bytes));
}
__device__ __forceinline__ void cp_commit() {
    asm volatile("cp.async.commit_group;\n" ::: "memory");
}
__device__ __forceinline__ void cp_wait1() {
    asm volatile("cp.async.wait_group 1;\n" ::: "memory");
}
__device__ __forceinline__ void cp_wait0() {
    asm volatile("cp.async.wait_group 0;\n" ::: "memory");
}

// ---------------- small utility kernels ----------------
__global__ void reset_kernel() {
    int i = threadIdx.x;
    if (i < NE) { g_count[i] = 0; g_frac_acc[i] = 0.f; }
}

__global__ void prep_kernel(const float* __restrict__ sim, const float* __restrict__ temp) {
    int w = threadIdx.x >> 5, lane = threadIdx.x & 31;
    float ss = 0.f;
    for (int i = 0; i < PD/32; i++) {
        float v = sim[(lane + 32*i)*NE + w];
        ss += v*v;
    }
    #pragma unroll
    for (int off = 16; off; off >>= 1) ss += __shfl_xor_sync(0xffffffff, ss, off);
    if (lane == 0) g_inv_simnorm[w] = 1.f / fmaxf(sqrtf(ss), 1e-12f);
    if (threadIdx.x == 0) g_scale = expf(fminf(temp[0], CLAMP_MAX));
}

// ---------------- projection: proj = x @ Wp^T + bp (fp32 SIMT, exact) ----------------
__global__ void proj_kernel(const float* __restrict__ x, const float* __restrict__ Wp,
                            const float* __restrict__ bp) {
    const int BM = 64, BN = 64, BK = 16;
    __shared__ float Xs[BK][BM+2];
    __shared__ float Ws[BK][BN+2];
    int m0 = blockIdx.x * BM, n0 = blockIdx.y * BN;
    int tid = threadIdx.x;
    int ty = tid >> 4, tx = tid & 15;
    float acc[4][4];
    #pragma unroll
    for (int i = 0; i < 4; i++)
        #pragma unroll
        for (int j = 0; j < 4; j++) acc[i][j] = 0.f;

    for (int k0 = 0; k0 < DM; k0 += BK) {
        for (int idx = tid; idx < BM*BK; idx += 256) {
            int m = idx >> 4, k = idx & 15;
            Xs[k][m] = x[(size_t)(m0+m)*DM + k0 + k];
            Ws[k][m] = Wp[(size_t)(n0+m)*DM + k0 + k];
        }
        __syncthreads();
        #pragma unroll
        for (int k = 0; k < BK; k++) {
            float a[4], b[4];
            #pragma unroll
            for (int i = 0; i < 4; i++) a[i] = Xs[k][ty*4+i];
            #pragma unroll
            for (int j = 0; j < 4; j++) b[j] = Ws[k][tx*4+j];
            #pragma unroll
            for (int i = 0; i < 4; i++)
                #pragma unroll
                for (int j = 0; j < 4; j++) acc[i][j] += a[i]*b[j];
        }
        __syncthreads();
    }
    #pragma unroll
    for (int i = 0; i < 4; i++)
        #pragma unroll
        for (int j = 0; j < 4; j++) {
            int n = n0 + tx*4 + j;
            g_proj[(size_t)(m0+ty*4+i)*PD + n] = acc[i][j] + bp[n];
        }
}

// ---------------- gating: softmax over cosine sims, top-2, routing stats ----------------
__global__ void gate_kernel(const float* __restrict__ sim) {
    int t = blockIdx.x * 8 + (threadIdx.x >> 5);
    int lane = threadIdx.x & 31;
    float pv[PD/32];
    float ss = 0.f;
    #pragma unroll
    for (int i = 0; i < PD/32; i++) {
        pv[i] = g_proj[(size_t)t*PD + lane + 32*i];
        ss += pv[i]*pv[i];
    }
    #pragma unroll
    for (int off = 16; off; off >>= 1) ss += __shfl_xor_sync(0xffffffff, ss, off);
    float inv_pn = 1.f / fmaxf(sqrtf(ss), 1e-12f);
    float scale = g_scale;
    float logit[NE];
    #pragma unroll
    for (int e = 0; e < NE; e++) {
        float d = 0.f;
        #pragma unroll
        for (int i = 0; i < PD/32; i++)
            d += pv[i] * sim[(lane + 32*i)*NE + e];
        #pragma unroll
        for (int off = 16; off; off >>= 1) d += __shfl_xor_sync(0xffffffff, d, off);
        logit[e] = d * inv_pn * g_inv_simnorm[e] * scale;
    }
    float mx = logit[0];
    #pragma unroll
    for (int e = 1; e < NE; e++) mx = fmaxf(mx, logit[e]);
    float pr[NE], se = 0.f;
    #pragma unroll
    for (int e = 0; e < NE; e++) { pr[e] = expf(logit[e]-mx); se += pr[e]; }
    float inv_se = 1.f / se;
    #pragma unroll
    for (int e = 0; e < NE; e++) pr[e] *= inv_se;
    int i0 = 0;
    #pragma unroll
    for (int e = 1; e < NE; e++) if (pr[e] > pr[i0]) i0 = e;
    int i1 = (i0 == 0) ? 1 : 0;
    #pragma unroll
    for (int e = 0; e < NE; e++) if (e != i0 && pr[e] > pr[i1]) i1 = e;
    float s = pr[i0] + pr[i1] + 1e-8f;
    float w0 = pr[i0]/s, w1 = pr[i1]/s;
    if (lane == 0) {
        g_topk_e[t*2]   = i0; g_topk_e[t*2+1] = i1;
        g_topk_w[t*2]   = w0; g_topk_w[t*2+1] = w1;
        g_sumw[t] = w0 + w1;
        atomicAdd(&g_count[i0], 1);
        atomicAdd(&g_count[i1], 1);
    }
    if (lane < NE) atomicAdd(&g_frac_acc[lane], pr[lane]);
}

__global__ void scan_kernel() {
    int off = 0, toff = 0;
    for (int e = 0; e < NE; e++) {
        g_offset[e]  = off;
        g_tileoff[e] = toff;
        g_cursor[e]  = off;
        off  += g_count[e];
        toff += (g_count[e] + BMM - 1) >> 7;
    }
    g_offset[NE]  = off;
    g_tileoff[NE] = toff;
}

__global__ void build_kernel() {
    int i = blockIdx.x * blockDim.x + threadIdx.x;
    if (i >= TK) return;
    int e = g_topk_e[i];
    int row = atomicAdd(&g_cursor[e], 1);
    g_token_of_row[row] = i >> 1;
    g_w_of_row[row]     = g_topk_w[i];
}

__global__ void init_out_kernel(const float* __restrict__ x, float* __restrict__ out) {
    size_t i = (size_t)blockIdx.x * blockDim.x + threadIdx.x;
    out[i] = g_sumw[i >> 10] * x[i];
}

// ---------------- TF32 WMMA grouped GEMMs: 128x128x32, cp.async double-buffer ----------------
// 8 warps, each computes a 64x32 warp tile (4x2 accumulator frags).

__global__ __launch_bounds__(256) void gemm1_kernel(const float* __restrict__ x,
                                                    const float* __restrict__ A,
                                                    const float* __restrict__ a_bias) {
    extern __shared__ float dyn[];
    __shared__ int s_tok[BMM];

    int bt = blockIdx.x;
    if (bt >= g_tileoff[NE]) return;
    int e = 0;
    while (bt >= g_tileoff[e+1]) e++;
    int mloc = bt - g_tileoff[e];
    int rowbase = g_offset[e] + mloc*BMM;
    int nrows = g_count[e] - mloc*BMM; if (nrows > BMM) nrows = BMM;
    int n0 = blockIdx.y * BNN;
    int tid = threadIdx.x;
    int wid = tid >> 5;
    int wm = wid >> 2, wn = wid & 3;

    if (tid < BMM) s_tok[tid] = (tid < nrows) ? g_token_of_row[rowbase + tid] : -1;
    __syncthreads();

    float* Xb0 = dyn;
    float* Xb1 = dyn + 128*XLD;
    float* Bb0 = dyn + 2*128*XLD;
    float* Bb1 = dyn + 3*128*XLD;
    const float* Aex = A + (size_t)e*HD*DM;

    auto load_tile = [&](int it, int buf) {
        int k0 = it * BKK;
        float* Xd = buf ? Xb1 : Xb0;
        float* Bd = buf ? Bb1 : Bb0;
        #pragma unroll
        for (int i = 0; i < 4; i++) {
            int c = tid + 256*i;
            int row = c >> 3, seg = c & 7;
            int tkn = s_tok[row];
            const float* src = (tkn >= 0) ? x + (size_t)tkn*DM + k0 + seg*4 : x;
            cp_async16(Xd + row*XLD + seg*4, src, (tkn >= 0) ? 16 : 0);
        }
        #pragma unroll
        for (int i = 0; i < 4; i++) {
            int c = tid + 256*i;
            int row = c >> 3, seg = c & 7;
            cp_async16(Bd + row*XLD + seg*4, Aex + (size_t)(n0 + row)*DM + k0 + seg*4, 16);
        }
    };

    wmma::fragment<wmma::accumulator,16,16,8,float> cfr[4][2];
    #pragma unroll
    for (int i = 0; i < 4; i++)
        #pragma unroll
        for (int j = 0; j < 2; j++) wmma::fill_fragment(cfr[i][j], 0.f);

    const int nk = DM / BKK;   // 32
    load_tile(0, 0); cp_commit();
    load_tile(1, 1); cp_commit();

    for (int it = 0; it < nk; it++) {
        if (it < nk-1) cp_wait1(); else cp_wait0();
        __syncthreads();
        float* Xs = (it & 1) ? Xb1 : Xb0;
        float* Bs = (it & 1) ? Bb1 : Bb0;
        #pragma unroll
        for (int kk = 0; kk < BKK; kk += 8) {
            wmma::fragment<wmma::matrix_a,16,16,8,wmma::precision::tf32,wmma::row_major> a[4];
            wmma::fragment<wmma::matrix_b,16,16,8,wmma::precision::tf32,wmma::col_major> b[2];
            #pragma unroll
            for (int i = 0; i < 4; i++) {
                wmma::load_matrix_sync(a[i], &Xs[(wm*64 + i*16)*XLD + kk], XLD);
                #pragma unroll
                for (int q = 0; q < a[i].num_elements; q++) a[i].x[q] = wmma::__float_to_tf32(a[i].x[q]);
            }
            #pragma unroll
            for (int j = 0; j < 2; j++) {
                wmma::load_matrix_sync(b[j], &Bs[(wn*32 + j*16)*XLD + kk], XLD);
                #pragma unroll
                for (int q = 0; q < b[j].num_elements; q++) b[j].x[q] = wmma::__float_to_tf32(b[j].x[q]);
            }
            #pragma unroll
            for (int i = 0; i < 4; i++)
                #pragma unroll
                for (int j = 0; j < 2; j++)
                    wmma::mma_sync(cfr[i][j], a[i], b[j], cfr[i][j]);
        }
        __syncthreads();
        if (it + 2 < nk) { load_tile(it+2, it & 1); cp_commit(); }
    }

    // epilogue: stage through smem (reuses the load buffers), add bias, scatter to g_H
    float* Cs = dyn;
    #pragma unroll
    for (int i = 0; i < 4; i++)
        #pragma unroll
        for (int j = 0; j < 2; j++)
            wmma::store_matrix_sync(&Cs[(wm*64 + i*16)*CLD + wn*32 + j*16], cfr[i][j], CLD, wmma::mem_row_major);
    __syncthreads();
    for (int idx = tid; idx < BMM*BNN; idx += 256) {
        int r = idx >> 7, n = idx & 127;
        if (r < nrows)
            g_H[(size_t)(rowbase+r)*HD + n0 + n] = Cs[r*CLD + n] + a_bias[(size_t)e*HD + n0 + n];
    }
}

__global__ __launch_bounds__(256) void gemm2_kernel(const float* __restrict__ Bw,
                                                    const float* __restrict__ b_bias,
                                                    float* __restrict__ out) {
    extern __shared__ float dyn[];
    __shared__ int   s_tok[BMM];
    __shared__ float s_w[BMM];

    int bt = blockIdx.x;
    if (bt >= g_tileoff[NE]) return;
    int e = 0;
    while (bt >= g_tileoff[e+1]) e++;
    int mloc = bt - g_tileoff[e];
    int rowbase = g_offset[e] + mloc*BMM;
    int nrows = g_count[e] - mloc*BMM; if (nrows > BMM) nrows = BMM;
    int n0 = blockIdx.y * BNN;
    int tid = threadIdx.x;
    int wid = tid >> 5;
    int wm = wid >> 2, wn = wid & 3;

    if (tid < BMM) {
        s_tok[tid] = (tid < nrows) ? g_token_of_row[rowbase + tid] : -1;
        s_w[tid]   = (tid < nrows) ? g_w_of_row[rowbase + tid] : 0.f;
    }
    __syncthreads();

    float* Xb0 = dyn;
    float* Xb1 = dyn + 128*XLD;
    float* Bb0 = dyn + 2*128*XLD;
    float* Bb1 = dyn + 3*128*XLD;
    const float* Bex = Bw + (size_t)e*DM*HD;

    auto load_tile = [&](int it, int buf) {
        int k0 = it * BKK;
        float* Xd = buf ? Xb1 : Xb0;
        float* Bd = buf ? Bb1 : Bb0;
        #pragma unroll
        for (int i = 0; i < 4; i++) {
            int c = tid + 256*i;
            int row = c >> 3, seg = c & 7;
            bool v = (row < nrows);
            const float* src = v ? g_H + (size_t)(rowbase+row)*HD + k0 + seg*4 : g_H;
            cp_async16(Xd + row*XLD + seg*4, src, v ? 16 : 0);
        }
        #pragma unroll
        for (int i = 0; i < 4; i++) {
            int c = tid + 256*i;
            int row = c >> 3, seg = c & 7;
            cp_async16(Bd + row*XLD + seg*4, Bex + (size_t)(n0 + row)*HD + k0 + seg*4, 16);
        }
    };

    wmma::fragment<wmma::accumulator,16,16,8,float> cfr[4][2];
    #pragma unroll
    for (int i = 0; i < 4; i++)
        #pragma unroll
        for (int j = 0; j < 2; j++) wmma::fill_fragment(cfr[i][j], 0.f);

    const int nk = HD / BKK;   // 128
    load_tile(0, 0); cp_commit();
    load_tile(1, 1); cp_commit();

    for (int it = 0; it < nk; it++) {
        if (it < nk-1) cp_wait1(); else cp_wait0();
        __syncthreads();
        float* Xs = (it & 1) ? Xb1 : Xb0;
        float* Bs = (it & 1) ? Bb1 : Bb0;
        #pragma unroll
        for (int kk = 0; kk < BKK; kk += 8) {
            wmma::fragment<wmma::matrix_a,16,16,8,wmma::precision::tf32,wmma::row_major> a[4];
            wmma::fragment<wmma::matrix_b,16,16,8,wmma::precision::tf32,wmma::col_major> b[2];
            #pragma unroll
            for (int i = 0; i < 4; i++) {
                wmma::load_matrix_sync(a[i], &Xs[(wm*64 + i*16)*XLD + kk], XLD);
                #pragma unroll
                for (int q = 0; q < a[i].num_elements; q++) a[i].x[q] = wmma::__float_to_tf32(a[i].x[q]);
            }
            #pragma unroll
            for (int j = 0; j < 2; j++) {
                wmma::load_matrix_sync(b[j], &Bs[(wn*32 + j*16)*XLD + kk], XLD);
                #pragma unroll
                for (int q = 0; q < b[j].num_elements; q++) b[j].x[q] = wmma::__float_to_tf32(b[j].x[q]);
            }
            #pragma unroll
            for (int i = 0; i < 4; i++)
                #pragma unroll
                for (int j = 0; j < 2; j++)
                    wmma::mma_sync(cfr[i][j], a[i], b[j], cfr[i][j]);
        }
        __syncthreads();
        if (it + 2 < nk) { load_tile(it+2, it & 1); cp_commit(); }
    }

    float* Cs = dyn;
    #pragma unroll
    for (int i = 0; i < 4; i++)
        #pragma unroll
        for (int j = 0; j < 2; j++)
            wmma::store_matrix_sync(&Cs[(wm*64 + i*16)*CLD + wn*32 + j*16], cfr[i][j], CLD, wmma::mem_row_major);
    __syncthreads();
    for (int idx = tid; idx < BMM*BNN; idx += 256) {
        int r = idx >> 7, n = idx & 127;
        if (r < nrows) {
            float v = Cs[r*CLD + n] + b_bias[(size_t)e*DM + n0 + n];
            atomicAdd(&out[(size_t)s_tok[r]*DM + n0 + n], s_w[r] * v);
        }
    }
}

__global__ void finalize_kernel(float* __restrict__ out) {
    if (threadIdx.x != 0) return;
    const size_t base = (size_t)TOK * DM;
    float aux = 0.f;
    for (int e = 0; e < NE; e++) {
        float fr = g_frac_acc[e] / (float)TOK;
        float d = fr - 1.f/(float)NE;
        aux += d*d;
        out[base + 1 + e]  = fr;
        out[base + 9 + e]  = (float)g_count[e];
    }
    out[base] = aux;
}

// ---------------- launch ----------------
extern "C" void kernel_launch(void* const* d_in, const int* in_sizes, int n_in,
                              void* d_out, int out_size) {
    const float* x      = (const float*)d_in[0];
    const float* Wp     = (const float*)d_in[1];
    const float* bp     = (const float*)d_in[2];
    const float* sim    = (const float*)d_in[3];
    const float* temp   = (const float*)d_in[4];
    const float* A      = (const float*)d_in[5];
    const float* a_bias = (const float*)d_in[6];
    const float* Bw     = (const float*)d_in[7];
    const float* b_bias = (const float*)d_in[8];
    float* out = (float*)d_out;

    // cudaFuncSetAttribute is idempotent device-state config (not a stream op,
    // not an allocation) — safe under graph capture; call unconditionally.
    cudaFuncSetAttribute(gemm1_kernel, cudaFuncAttributeMaxDynamicSharedMemorySize, GEMM_SMEM);
    cudaFuncSetAttribute(gemm2_kernel, cudaFuncAttributeMaxDynamicSharedMemorySize, GEMM_SMEM);

    reset_kernel<<<1, 32>>>();
    prep_kernel<<<1, 256>>>(sim, temp);
    proj_kernel<<<dim3(TOK/64, PD/64), 256>>>(x, Wp, bp);
    gate_kernel<<<TOK/8, 256>>>(sim);
    scan_kernel<<<1, 1>>>();
    build_kernel<<<TK/256, 256>>>();
    init_out_kernel<<<(TOK*DM)/256, 256>>>(x, out);
    gemm1_kernel<<<dim3(NTILES, HD/BNN), 256, GEMM_SMEM>>>(x, A, a_bias);
    gemm2_kernel<<<dim3(NTILES, DM/BNN), 256, GEMM_SMEM>>>(Bw, b_bias, out);
    finalize_kernel<<<1, 32>>>(out);
}